// round 3
// baseline (speedup 1.0000x reference)
#include <cuda_runtime.h>
#include <cstdint>

#define T_SEQ 1024
#define BATCH 256
#define ISZ   128
#define HSZ   64
#define GSZ   256   // 4*H
#define NBP   128   // BATCH/2 (batch pairs)
#define NCLS  10

typedef unsigned long long ull;

// Scratch (device globals — allocation-free per harness rules)
// Layout: [t][bp][g] of float2{batch 2bp, batch 2bp+1}
__device__ float2 g_xproj[(size_t)T_SEQ * NBP * GSZ];   // 268 MB
__device__ ull    g_hT[NBP * HSZ];                      // final hidden, packed pairs

// ---------- helpers ----------
union F2U { float2 f2; ull u; };

__device__ __forceinline__ ull pack2(float lo, float hi) {
    F2U t; t.f2 = make_float2(lo, hi); return t.u;
}
__device__ __forceinline__ float2 unpack2(ull v) {
    F2U t; t.u = v; return t.f2;
}
__device__ __forceinline__ ull ffma2(ull a, ull b, ull c) {
    ull d;
    asm("fma.rn.f32x2 %0, %1, %2, %3;" : "=l"(d) : "l"(a), "l"(b), "l"(c));
    return d;
}
__device__ __forceinline__ ull fadd2(ull a, ull b) {
    ull d;
    asm("add.rn.f32x2 %0, %1, %2;" : "=l"(d) : "l"(a), "l"(b));
    return d;
}
__device__ __forceinline__ unsigned f2tf32(float f) {
    unsigned r;
    asm("cvt.rna.tf32.f32 %0, %1;" : "=r"(r) : "f"(f));
    return r;
}

// =====================================================================
// Kernel A: x_proj[t][bp][g] = {x[2bp,t]·W_ih[g] + bias, x[2bp+1,t]·W_ih[g] + bias}
// tf32 mma.sync, CTA tile: 16 t-rows x 128 g-cols x 2 batches, K chunked 64.
// =====================================================================
__global__ __launch_bounds__(128) void xproj_kernel(
    const float* __restrict__ x, const float* __restrict__ W_ih,
    const float* __restrict__ b_ih, const float* __restrict__ b_hh)
{
    __shared__ float As[2][16][68];     // [batch][t][k] pad->68 (272B rows, 16B aligned)
    __shared__ float Ws[128][68];       // [g][k]
    __shared__ float bias_s[128];

    const int tid  = threadIdx.x;
    const int warp = tid >> 5, lane = tid & 31;
    const int gid  = lane >> 2, tig = lane & 3;   // mma groupID / threadID-in-group
    const int gbase = blockIdx.x * 128;
    const int t0    = blockIdx.y * 16;
    const int bp    = blockIdx.z;
    const int b0g   = bp * 2;

    bias_s[tid] = b_ih[gbase + tid] + b_hh[gbase + tid];

    float acc[2][4][4];
    #pragma unroll
    for (int b = 0; b < 2; b++)
        #pragma unroll
        for (int n = 0; n < 4; n++)
            #pragma unroll
            for (int i = 0; i < 4; i++) acc[b][n][i] = 0.f;

    for (int kc = 0; kc < 128; kc += 64) {
        // Load A tiles: 2 x 16 x 64 floats (512 float4)
        #pragma unroll
        for (int r = 0; r < 4; ++r) {
            int idx = tid + r * 128;
            int b   = idx >> 8;
            int rem = idx & 255;
            int tt  = rem >> 4;
            int v   = rem & 15;
            float4 src = *(const float4*)&x[(((size_t)(b0g + b)) * T_SEQ + (t0 + tt)) * ISZ + kc + v * 4];
            *(float4*)&As[b][tt][v * 4] = src;
        }
        // Load W tile: 128 x 64 floats (2048 float4 elems -> 512 float4)
        #pragma unroll
        for (int r = 0; r < 16; ++r) {
            int idx = tid + r * 128;
            int gg  = idx >> 4;
            int v   = idx & 15;
            float4 src = *(const float4*)&W_ih[((size_t)(gbase + gg)) * ISZ + kc + v * 4];
            *(float4*)&Ws[gg][v * 4] = src;
        }
        __syncthreads();

        #pragma unroll
        for (int ks = 0; ks < 8; ++ks) {
            const int k0 = ks * 8;
            unsigned a[2][4];
            #pragma unroll
            for (int b = 0; b < 2; b++) {
                a[b][0] = f2tf32(As[b][gid    ][k0 + tig]);
                a[b][1] = f2tf32(As[b][gid + 8][k0 + tig]);
                a[b][2] = f2tf32(As[b][gid    ][k0 + tig + 4]);
                a[b][3] = f2tf32(As[b][gid + 8][k0 + tig + 4]);
            }
            #pragma unroll
            for (int nt = 0; nt < 4; nt++) {
                const int nl = warp * 32 + nt * 8 + gid;
                unsigned bb0 = f2tf32(Ws[nl][k0 + tig]);
                unsigned bb1 = f2tf32(Ws[nl][k0 + tig + 4]);
                #pragma unroll
                for (int b = 0; b < 2; b++) {
                    asm volatile(
                        "mma.sync.aligned.m16n8k8.row.col.f32.tf32.tf32.f32 "
                        "{%0,%1,%2,%3}, {%4,%5,%6,%7}, {%8,%9}, {%0,%1,%2,%3};"
                        : "+f"(acc[b][nt][0]), "+f"(acc[b][nt][1]),
                          "+f"(acc[b][nt][2]), "+f"(acc[b][nt][3])
                        : "r"(a[b][0]), "r"(a[b][1]), "r"(a[b][2]), "r"(a[b][3]),
                          "r"(bb0), "r"(bb1));
                }
            }
        }
        __syncthreads();
    }

    // Epilogue: add bias, write paired float2 (as float4 covering 2 adjacent g)
    #pragma unroll
    for (int nt = 0; nt < 4; nt++) {
        const int nl  = warp * 32 + nt * 8 + 2 * tig;
        const float bs0 = bias_s[nl], bs1 = bias_s[nl + 1];
        const int ggl = gbase + nl;
        const int tr0 = t0 + gid, tr1 = t0 + gid + 8;
        float4 v0 = make_float4(acc[0][nt][0] + bs0, acc[1][nt][0] + bs0,
                                acc[0][nt][1] + bs1, acc[1][nt][1] + bs1);
        float4 v1 = make_float4(acc[0][nt][2] + bs0, acc[1][nt][2] + bs0,
                                acc[0][nt][3] + bs1, acc[1][nt][3] + bs1);
        *(float4*)&g_xproj[((size_t)tr0 * NBP + bp) * GSZ + ggl] = v0;
        *(float4*)&g_xproj[((size_t)tr1 * NBP + bp) * GSZ + ggl] = v1;
    }
}

// =====================================================================
// Kernel B: the recurrence. 128 CTAs (one batch pair each), 256 threads.
// Thread g computes gate-row g for both batches via packed fma.rn.f32x2;
// W_hh row held duplicated in 128 registers.
// =====================================================================
__global__ __launch_bounds__(256, 1) void lstm_kernel(const float* __restrict__ W_hh)
{
    __shared__ __align__(16) ull h_s[HSZ];
    __shared__ ull gate_s[GSZ];

    const int g   = threadIdx.x;
    const int bp  = blockIdx.x;
    const int j   = g & 63;
    const int sec = g >> 6;          // 0:i 1:f 2:g 3:o  (warp-uniform)

    // Load W_hh row g, duplicated into f32x2 pairs (128 registers)
    ull w2[HSZ];
    {
        const float4* wrow = (const float4*)&W_hh[g * HSZ];
        #pragma unroll
        for (int q = 0; q < 16; ++q) {
            float4 w = wrow[q];
            w2[q * 4 + 0] = pack2(w.x, w.x);
            w2[q * 4 + 1] = pack2(w.y, w.y);
            w2[q * 4 + 2] = pack2(w.z, w.z);
            w2[q * 4 + 3] = pack2(w.w, w.w);
        }
    }

    float c0 = 0.f, c1 = 0.f;
    if (g < HSZ) h_s[g] = 0ull;
    __syncthreads();

    const ull* xp_ptr = (const ull*)g_xproj;
    const size_t idx0 = (size_t)bp * GSZ + g;
    ull xp_cur = xp_ptr[idx0];     // t = 0

    for (int t = 0; t < T_SEQ; ++t) {
        // prefetch next step's x_proj
        ull xp_next = 0ull;
        if (t + 1 < T_SEQ) xp_next = xp_ptr[idx0 + (size_t)(t + 1) * (NBP * GSZ)];

        // gates[g] = xp + sum_k W_hh[g][k] * h[k]   (packed over the batch pair)
        ull acc0 = 0ull, acc1 = 0ull, acc2 = 0ull, acc3 = 0ull;
        const ulonglong2* h2 = (const ulonglong2*)h_s;
        #pragma unroll
        for (int kk = 0; kk < 16; ++kk) {
            ulonglong2 ha = h2[2 * kk];
            ulonglong2 hb = h2[2 * kk + 1];
            acc0 = ffma2(w2[4 * kk + 0], ha.x, acc0);
            acc1 = ffma2(w2[4 * kk + 1], ha.y, acc1);
            acc2 = ffma2(w2[4 * kk + 2], hb.x, acc2);
            acc3 = ffma2(w2[4 * kk + 3], hb.y, acc3);
        }
        ull gsum = fadd2(fadd2(acc0, acc1), fadd2(acc2, acc3));
        gsum = fadd2(gsum, xp_cur);
        xp_cur = xp_next;

        float2 gv = unpack2(gsum);
        float r0, r1;
        if (sec == 2) {                       // candidate gate: tanh
            r0 = tanhf(gv.x); r1 = tanhf(gv.y);
        } else {                              // i/f/o: sigmoid
            r0 = 1.f / (1.f + __expf(-gv.x));
            r1 = 1.f / (1.f + __expf(-gv.y));
        }
        gate_s[g] = pack2(r0, r1);
        __syncthreads();

        if (g < HSZ) {
            float2 iv = unpack2(gate_s[j]);
            float2 fv = unpack2(gate_s[64 + j]);
            float2 gg = unpack2(gate_s[128 + j]);
            float2 ov = unpack2(gate_s[192 + j]);
            c0 = fv.x * c0 + iv.x * gg.x;
            c1 = fv.y * c1 + iv.y * gg.y;
            float h0 = ov.x * tanhf(c0);
            float h1 = ov.y * tanhf(c1);
            ull hp = pack2(h0, h1);
            h_s[j] = hp;
            if (t == T_SEQ - 1) g_hT[bp * HSZ + j] = hp;
        }
        __syncthreads();
    }
}

// =====================================================================
// Kernel C: logits = h_T @ W_cls^T + b_cls   (256 x 10)
// =====================================================================
__global__ void cls_kernel(const float* __restrict__ W_cls,
                           const float* __restrict__ b_cls,
                           float* __restrict__ out)
{
    const int b = blockIdx.x, lane = threadIdx.x;
    const int bp = b >> 1, par = b & 1;
    float2 p0 = unpack2(g_hT[bp * HSZ + lane]);
    float2 p1 = unpack2(g_hT[bp * HSZ + lane + 32]);
    float h0 = par ? p0.y : p0.x;
    float h1 = par ? p1.y : p1.x;
    #pragma unroll
    for (int c = 0; c < NCLS; ++c) {
        float p = h0 * W_cls[c * HSZ + lane] + h1 * W_cls[c * HSZ + lane + 32];
        #pragma unroll
        for (int off = 16; off; off >>= 1)
            p += __shfl_xor_sync(0xffffffffu, p, off);
        if (lane == 0) out[b * NCLS + c] = p + b_cls[c];
    }
}

// =====================================================================
extern "C" void kernel_launch(void* const* d_in, const int* in_sizes, int n_in,
                              void* d_out, int out_size) {
    const float* x     = (const float*)d_in[0];
    const float* W_ih  = (const float*)d_in[1];
    const float* W_hh  = (const float*)d_in[2];
    const float* b_ih  = (const float*)d_in[3];
    const float* b_hh  = (const float*)d_in[4];
    const float* W_cls = (const float*)d_in[5];
    const float* b_cls = (const float*)d_in[6];
    float* out = (float*)d_out;

    dim3 gA(2, 64, 128);               // g-tiles x t-tiles x batch-pairs
    xproj_kernel<<<gA, 128>>>(x, W_ih, b_ih, b_hh);
    lstm_kernel<<<NBP, 256>>>(W_hh);
    cls_kernel<<<BATCH, 32>>>(W_cls, b_cls, out);
}